// round 1
// baseline (speedup 1.0000x reference)
#include <cuda_runtime.h>
#include <cuda_bf16.h>
#include <math.h>

// ---------------------------------------------------------------------------
// Problem constants
// ---------------------------------------------------------------------------
#define L_SEQ   2516          // 16 + 25*100
#define C_DIM   128
#define HEADS_N 8
#define DH      16
#define MLP_DIM 512
#define N_IMG   100           // 25 support + 75 query
#define HW      100           // 10x10
#define T_CH    32
#define KSPLIT  3
#define KSPAN   839           // ceil(2516/3)

// ---------------------------------------------------------------------------
// Scratch (device globals; no allocation allowed)
// ---------------------------------------------------------------------------
__device__ float g_X   [L_SEQ * C_DIM];
__device__ float g_H   [L_SEQ * C_DIM];
__device__ float g_QKV [L_SEQ * 3 * C_DIM];
__device__ float g_O   [L_SEQ * C_DIM];
__device__ float g_G   [L_SEQ * MLP_DIM];
__device__ float g_PART[KSPLIT * HEADS_N * L_SEQ * DH];
__device__ float g_ML  [KSPLIT * HEADS_N * L_SEQ * 2];
__device__ float g_FUSED[N_IMG * C_DIM * HW];
__device__ float g_LNT  [N_IMG * C_DIM * HW];
__device__ float g_T1   [N_IMG * T_CH * HW];
__device__ float g_T2   [N_IMG * T_CH * HW];

// ---------------------------------------------------------------------------
// build X = concat(task_descriptor, support permuted)
// ---------------------------------------------------------------------------
__global__ void build_x_k(const float* __restrict__ task,
                          const float* __restrict__ support,
                          float* __restrict__ X)
{
    int i = blockIdx.x * blockDim.x + threadIdx.x;
    if (i >= L_SEQ * C_DIM) return;
    int r = i >> 7;          // /128
    int c = i & 127;
    if (r < 16) {
        X[i] = task[r * C_DIM + c];
    } else {
        int rr = r - 16;
        int b = rr / HW, p = rr % HW;
        X[i] = support[b * C_DIM * HW + c * HW + p];
    }
}

// ---------------------------------------------------------------------------
// Row LayerNorm over last dim (128). One block (128 threads) per row.
// ---------------------------------------------------------------------------
__global__ void ln_rows_k(const float* __restrict__ X, const float* __restrict__ g,
                          const float* __restrict__ b, float* __restrict__ H, float eps)
{
    int r = blockIdx.x, t = threadIdx.x;
    float v = X[r * C_DIM + t];
    float s = v;
#pragma unroll
    for (int o = 16; o > 0; o >>= 1) s += __shfl_xor_sync(0xFFFFFFFFu, s, o);
    __shared__ float ws[4], ws2[4];
    int w = t >> 5, lane = t & 31;
    if (lane == 0) ws[w] = s;
    __syncthreads();
    float mean = (ws[0] + ws[1] + ws[2] + ws[3]) * (1.0f / 128.0f);
    float d = v - mean;
    float s2 = d * d;
#pragma unroll
    for (int o = 16; o > 0; o >>= 1) s2 += __shfl_xor_sync(0xFFFFFFFFu, s2, o);
    if (lane == 0) ws2[w] = s2;
    __syncthreads();
    float var = (ws2[0] + ws2[1] + ws2[2] + ws2[3]) * (1.0f / 128.0f);
    H[r * C_DIM + t] = d * rsqrtf(var + eps) * g[t] + b[t];
}

// ---------------------------------------------------------------------------
// Tiled GEMM  C[M,N] = A[M,K] @ B[K,N]  (+ epilogue)
// epi: 0 = +bias ; 1 = +bias+res ; 2 = gelu(+bias)
// BM=BN=64, BK=16, 256 threads, 4x4 per thread. K % 16 == 0, N % 64 == 0.
// ---------------------------------------------------------------------------
__global__ void gemm_epi_k(const float* __restrict__ A, const float* __restrict__ B,
                           const float* __restrict__ bias, const float* __restrict__ res,
                           float* __restrict__ C, int M, int N, int K, int epi)
{
    __shared__ __align__(16) float As[64][16];
    __shared__ __align__(16) float Bs[16][64];
    int bm = blockIdx.y * 64, bn = blockIdx.x * 64;
    int tid = threadIdx.x;
    int tx = tid & 15, ty = tid >> 4;
    float acc[4][4];
#pragma unroll
    for (int i = 0; i < 4; i++)
#pragma unroll
        for (int j = 0; j < 4; j++) acc[i][j] = 0.0f;

    int arow = tid >> 2, ak = (tid & 3) * 4;
    int brow = tid >> 4, bcol = (tid & 15) * 4;

    for (int k0 = 0; k0 < K; k0 += 16) {
        float4 av = make_float4(0.f, 0.f, 0.f, 0.f);
        if (bm + arow < M)
            av = *(const float4*)&A[(size_t)(bm + arow) * K + k0 + ak];
        *(float4*)&As[arow][ak] = av;
        float4 bv = *(const float4*)&B[(size_t)(k0 + brow) * N + bn + bcol];
        *(float4*)&Bs[brow][bcol] = bv;
        __syncthreads();
#pragma unroll
        for (int k = 0; k < 16; k++) {
            float a0 = As[ty * 4 + 0][k];
            float a1 = As[ty * 4 + 1][k];
            float a2 = As[ty * 4 + 2][k];
            float a3 = As[ty * 4 + 3][k];
            float4 b4 = *(const float4*)&Bs[k][tx * 4];
            acc[0][0] += a0 * b4.x; acc[0][1] += a0 * b4.y; acc[0][2] += a0 * b4.z; acc[0][3] += a0 * b4.w;
            acc[1][0] += a1 * b4.x; acc[1][1] += a1 * b4.y; acc[1][2] += a1 * b4.z; acc[1][3] += a1 * b4.w;
            acc[2][0] += a2 * b4.x; acc[2][1] += a2 * b4.y; acc[2][2] += a2 * b4.z; acc[2][3] += a2 * b4.w;
            acc[3][0] += a3 * b4.x; acc[3][1] += a3 * b4.y; acc[3][2] += a3 * b4.z; acc[3][3] += a3 * b4.w;
        }
        __syncthreads();
    }
#pragma unroll
    for (int i = 0; i < 4; i++) {
        int r = bm + ty * 4 + i;
        if (r >= M) continue;
#pragma unroll
        for (int j = 0; j < 4; j++) {
            int cidx = bn + tx * 4 + j;
            float v = acc[i][j] + bias[cidx];
            if (epi == 1) v += res[(size_t)r * N + cidx];
            else if (epi == 2) v = 0.5f * v * (1.0f + erff(v * 0.70710678118654752f));
            C[(size_t)r * N + cidx] = v;
        }
    }
}

// ---------------------------------------------------------------------------
// Flash-style attention, split over keys (KSPLIT). One thread per query.
// grid (qtiles=20, heads=8, splits=3), block 128.
// ---------------------------------------------------------------------------
__global__ void attn_partial_k(const float* __restrict__ QKV,
                               float* __restrict__ PART, float* __restrict__ ML)
{
    int h  = blockIdx.y;
    int sp = blockIdx.z;
    int q  = blockIdx.x * 128 + threadIdx.x;
    int k0 = sp * KSPAN;
    int k1 = min(L_SEQ, k0 + KSPAN);

    __shared__ __align__(16) float Ks[64][16];
    __shared__ __align__(16) float Vs[64][16];

    bool act = q < L_SEQ;
    float4 qv[4];
    if (act) {
#pragma unroll
        for (int u = 0; u < 4; u++)
            qv[u] = *(const float4*)&QKV[(size_t)q * 384 + h * 16 + 4 * u];
    }
    float m = -INFINITY, l = 0.0f;
    float4 acc[4];
#pragma unroll
    for (int u = 0; u < 4; u++) acc[u] = make_float4(0.f, 0.f, 0.f, 0.f);

    for (int kc = k0; kc < k1; kc += 64) {
        int n = min(64, k1 - kc);
        for (int idx = threadIdx.x; idx < n * 16; idx += 128) {
            int row = idx >> 4, d = idx & 15;
            Ks[row][d] = QKV[(size_t)(kc + row) * 384 + 128 + h * 16 + d];
            Vs[row][d] = QKV[(size_t)(kc + row) * 384 + 256 + h * 16 + d];
        }
        __syncthreads();
        if (act) {
            for (int j = 0; j < n; j++) {
                float s = 0.0f;
#pragma unroll
                for (int u = 0; u < 4; u++) {
                    float4 kk = *(const float4*)&Ks[j][4 * u];
                    s += qv[u].x * kk.x + qv[u].y * kk.y + qv[u].z * kk.z + qv[u].w * kk.w;
                }
                s *= 0.25f;  // dh^-0.5
                if (s > m) {
                    float corr = __expf(m - s);
                    l *= corr;
#pragma unroll
                    for (int u = 0; u < 4; u++) {
                        acc[u].x *= corr; acc[u].y *= corr; acc[u].z *= corr; acc[u].w *= corr;
                    }
                    m = s;
                }
                float p = __expf(s - m);
                l += p;
#pragma unroll
                for (int u = 0; u < 4; u++) {
                    float4 vv = *(const float4*)&Vs[j][4 * u];
                    acc[u].x += p * vv.x; acc[u].y += p * vv.y;
                    acc[u].z += p * vv.z; acc[u].w += p * vv.w;
                }
            }
        }
        __syncthreads();
    }
    if (act) {
        size_t idx = ((size_t)(sp * HEADS_N + h) * L_SEQ + q);
#pragma unroll
        for (int u = 0; u < 4; u++)
            *(float4*)&PART[idx * 16 + 4 * u] = acc[u];
        ML[idx * 2 + 0] = m;
        ML[idx * 2 + 1] = l;
    }
}

__global__ void attn_merge_k(const float* __restrict__ PART, const float* __restrict__ ML,
                             float* __restrict__ O)
{
    int t = blockIdx.x * blockDim.x + threadIdx.x;
    if (t >= HEADS_N * L_SEQ) return;
    int h = t / L_SEQ, q = t % L_SEQ;
    float mm[KSPLIT], ll[KSPLIT];
    float M = -INFINITY;
#pragma unroll
    for (int sp = 0; sp < KSPLIT; sp++) {
        size_t idx = ((size_t)(sp * HEADS_N + h) * L_SEQ + q);
        mm[sp] = ML[idx * 2 + 0];
        ll[sp] = ML[idx * 2 + 1];
        M = fmaxf(M, mm[sp]);
    }
    float wsum = 0.0f, w[KSPLIT];
#pragma unroll
    for (int sp = 0; sp < KSPLIT; sp++) {
        w[sp] = __expf(mm[sp] - M);
        wsum += ll[sp] * w[sp];
    }
    float inv = 1.0f / wsum;
#pragma unroll
    for (int d = 0; d < DH; d++) {
        float o = 0.0f;
#pragma unroll
        for (int sp = 0; sp < KSPLIT; sp++) {
            size_t idx = ((size_t)(sp * HEADS_N + h) * L_SEQ + q);
            o += PART[idx * 16 + d] * w[sp];
        }
        O[(size_t)q * C_DIM + h * DH + d] = o * inv;
    }
}

// ---------------------------------------------------------------------------
// region + map_fuse: one block per image, thread per pixel.
// ---------------------------------------------------------------------------
__global__ void region_fuse_k(const float* __restrict__ support, const float* __restrict__ query,
                              const float* __restrict__ X, float* __restrict__ F)
{
    int img = blockIdx.x;
    __shared__ float key[16 * C_DIM];
    for (int i = threadIdx.x; i < 16 * C_DIM; i += 128) key[i] = X[i];
    __syncthreads();
    const float* feat = (img < 25) ? support + (size_t)img * C_DIM * HW
                                   : query + (size_t)(img - 25) * C_DIM * HW;
    float* fb = F + (size_t)img * C_DIM * HW;
    int p = threadIdx.x;
    if (p < HW) {
        float dot[16];
#pragma unroll
        for (int m = 0; m < 16; m++) dot[m] = 0.0f;
        for (int c = 0; c < C_DIM; c++) {
            float f = feat[c * HW + p];
#pragma unroll
            for (int m = 0; m < 16; m++) dot[m] += key[m * C_DIM + c] * f;
        }
        float s = 0.0f;
#pragma unroll
        for (int m = 0; m < 16; m++)
            s += 1.0f / (1.0f + __expf(-dot[m] * (1.0f / 128.0f)));
        s = s * (1.0f / 16.0f) + 1.0f;
        for (int c = 0; c < C_DIM; c++)
            fb[c * HW + p] = feat[c * HW + p] * s;
    }
}

// ---------------------------------------------------------------------------
// channel LayerNorm: per (image, pixel) over 128 channels. eps 1e-6.
// ---------------------------------------------------------------------------
__global__ void ln_chan_k(const float* __restrict__ F, const float* __restrict__ g,
                          const float* __restrict__ b, float* __restrict__ Out)
{
    int img = blockIdx.x;
    int p = threadIdx.x;
    if (p >= HW) return;
    const float* fb = F + (size_t)img * C_DIM * HW;
    float s = 0.0f;
    for (int c = 0; c < C_DIM; c++) s += fb[c * HW + p];
    float mean = s * (1.0f / 128.0f);
    float v = 0.0f;
    for (int c = 0; c < C_DIM; c++) {
        float d = fb[c * HW + p] - mean;
        v += d * d;
    }
    v *= (1.0f / 128.0f);
    float rs = rsqrtf(v + 1e-6f);
    float* ob = Out + (size_t)img * C_DIM * HW;
    for (int c = 0; c < C_DIM; c++)
        ob[c * HW + p] = (fb[c * HW + p] - mean) * rs * g[c] + b[c];
}

// ---------------------------------------------------------------------------
// 3x3 conv, pad 1, 10x10, Cout=32. Block per image (256 thr).
// Input cached in padded smem (Cin x 12 x 12). oc = tid>>3, 13 pixels/thread.
// ---------------------------------------------------------------------------
__global__ void conv3x3_k(const float* __restrict__ in, const float* __restrict__ w,
                          float* __restrict__ out, int Cin, int do_relu)
{
    extern __shared__ float s_in[];  // Cin*144
    int img = blockIdx.x;
    int tid = threadIdx.x;
    const float* inb = in + (size_t)img * Cin * HW;
    for (int idx = tid; idx < Cin * 144; idx += 256) {
        int c = idx / 144, pos = idx % 144;
        int y = pos / 12 - 1, x = pos % 12 - 1;
        float v = 0.0f;
        if (y >= 0 && y < 10 && x >= 0 && x < 10) v = inb[c * HW + y * 10 + x];
        s_in[idx] = v;
    }
    __syncthreads();

    int oc = tid >> 3, lane = tid & 7;
    float acc[13];
    int base[13];
#pragma unroll
    for (int t = 0; t < 13; t++) {
        acc[t] = 0.0f;
        int p = lane + 8 * t;
        if (p > 99) p = 99;           // clamp (dup compute, store guarded)
        int y = p / 10, x = p % 10;
        base[t] = y * 12 + x;
    }
    const float* wb = w + (size_t)oc * Cin * 9;
    for (int c = 0; c < Cin; c++) {
        const float* sc = s_in + c * 144;
#pragma unroll
        for (int kk = 0; kk < 9; kk++) {
            float wv = wb[c * 9 + kk];
            int off = (kk / 3) * 12 + (kk % 3);
#pragma unroll
            for (int t = 0; t < 13; t++)
                acc[t] += sc[base[t] + off] * wv;
        }
    }
    float* ob = out + (size_t)img * T_CH * HW + oc * HW;
#pragma unroll
    for (int t = 0; t < 13; t++) {
        int p = lane + 8 * t;
        if (p < HW) {
            float v = acc[t];
            if (do_relu) v = fmaxf(v, 0.0f);
            ob[p] = v;
        }
    }
}

// ---------------------------------------------------------------------------
// Final: out[b][c][t] = (1/100) * sum_p sigmoid(T4[b][t][p]) * F[b][c][p]
// Output layout: support block (25*128*32) then query block (75*128*32).
// ---------------------------------------------------------------------------
__global__ void rfm_out_k(const float* __restrict__ T4, const float* __restrict__ F,
                          float* __restrict__ out)
{
    int img = blockIdx.x;
    __shared__ float sig[HW * T_CH];  // [p][t]
    int tid = threadIdx.x;
    for (int idx = tid; idx < T_CH * HW; idx += 256) {
        int t = idx / HW, p = idx % HW;
        float v = T4[(size_t)img * T_CH * HW + idx];
        sig[p * T_CH + t] = 1.0f / (1.0f + __expf(-v));
    }
    __syncthreads();
    float* ob = out + ((img < 25) ? (size_t)img * 4096
                                  : (size_t)25 * 4096 + (size_t)(img - 25) * 4096);
    const float* fb = F + (size_t)img * C_DIM * HW;
    for (int o = tid; o < C_DIM * T_CH; o += 256) {
        int c = o >> 5, t = o & 31;
        float s = 0.0f;
        for (int p = 0; p < HW; p++)
            s += fb[c * HW + p] * sig[p * T_CH + t];
        ob[c * T_CH + t] = s * (1.0f / 100.0f);
    }
}

// ---------------------------------------------------------------------------
// Host launcher
// ---------------------------------------------------------------------------
extern "C" void kernel_launch(void* const* d_in, const int* in_sizes, int n_in,
                              void* d_out, int out_size)
{
    const float* support = (const float*)d_in[0];
    const float* query   = (const float*)d_in[1];
    const float* task    = (const float*)d_in[2];
    const float* ln1_g   = (const float*)d_in[3];
    const float* ln1_b   = (const float*)d_in[4];
    const float* qkv_w   = (const float*)d_in[5];
    const float* qkv_b   = (const float*)d_in[6];
    const float* out_w   = (const float*)d_in[7];
    const float* out_b   = (const float*)d_in[8];
    const float* ln2_g   = (const float*)d_in[9];
    const float* ln2_b   = (const float*)d_in[10];
    const float* mlp_w1  = (const float*)d_in[11];
    const float* mlp_b1  = (const float*)d_in[12];
    const float* mlp_w2  = (const float*)d_in[13];
    const float* mlp_b2  = (const float*)d_in[14];
    const float* rln_g   = (const float*)d_in[15];
    const float* rln_b   = (const float*)d_in[16];
    const float* conv1   = (const float*)d_in[17];
    const float* conv2   = (const float*)d_in[18];
    const float* conv3   = (const float*)d_in[19];
    const float* conv4   = (const float*)d_in[20];

    float *X, *H, *QKV, *O, *G, *PART, *ML, *FUSED, *LNT, *T1, *T2;
    cudaGetSymbolAddress((void**)&X, g_X);
    cudaGetSymbolAddress((void**)&H, g_H);
    cudaGetSymbolAddress((void**)&QKV, g_QKV);
    cudaGetSymbolAddress((void**)&O, g_O);
    cudaGetSymbolAddress((void**)&G, g_G);
    cudaGetSymbolAddress((void**)&PART, g_PART);
    cudaGetSymbolAddress((void**)&ML, g_ML);
    cudaGetSymbolAddress((void**)&FUSED, g_FUSED);
    cudaGetSymbolAddress((void**)&LNT, g_LNT);
    cudaGetSymbolAddress((void**)&T1, g_T1);
    cudaGetSymbolAddress((void**)&T2, g_T2);

    cudaFuncSetAttribute(conv3x3_k, cudaFuncAttributeMaxDynamicSharedMemorySize,
                         C_DIM * 144 * sizeof(float));

    // Build sequence
    build_x_k<<<(L_SEQ * C_DIM + 255) / 256, 256>>>(task, support, X);

    // Transformer (2 layers)
    for (int i = 0; i < 2; i++) {
        ln_rows_k<<<L_SEQ, 128>>>(X, ln1_g + i * C_DIM, ln1_b + i * C_DIM, H, 1e-5f);
        gemm_epi_k<<<dim3(6, 40), 256>>>(H, qkv_w + (size_t)i * C_DIM * 384,
                                         qkv_b + i * 384, nullptr, QKV,
                                         L_SEQ, 384, C_DIM, 0);
        attn_partial_k<<<dim3(20, HEADS_N, KSPLIT), 128>>>(QKV, PART, ML);
        attn_merge_k<<<(HEADS_N * L_SEQ + 127) / 128, 128>>>(PART, ML, O);
        gemm_epi_k<<<dim3(2, 40), 256>>>(O, out_w + (size_t)i * C_DIM * C_DIM,
                                         out_b + i * C_DIM, X, X,
                                         L_SEQ, C_DIM, C_DIM, 1);
        ln_rows_k<<<L_SEQ, 128>>>(X, ln2_g + i * C_DIM, ln2_b + i * C_DIM, H, 1e-5f);
        gemm_epi_k<<<dim3(8, 40), 256>>>(H, mlp_w1 + (size_t)i * C_DIM * MLP_DIM,
                                         mlp_b1 + i * MLP_DIM, nullptr, G,
                                         L_SEQ, MLP_DIM, C_DIM, 2);
        gemm_epi_k<<<dim3(2, 40), 256>>>(G, mlp_w2 + (size_t)i * MLP_DIM * C_DIM,
                                         mlp_b2 + i * C_DIM, X, X,
                                         L_SEQ, C_DIM, MLP_DIM, 1);
    }

    // Region + fuse (support 25 + query 75, one buffer)
    region_fuse_k<<<N_IMG, 128>>>(support, query, X, FUSED);
    ln_chan_k<<<N_IMG, 128>>>(FUSED, rln_g, rln_b, LNT);

    // RFM convs
    conv3x3_k<<<N_IMG, 256, C_DIM * 144 * sizeof(float)>>>(LNT, conv1, T1, C_DIM, 1);
    conv3x3_k<<<N_IMG, 256, T_CH * 144 * sizeof(float)>>>(T1, conv2, T2, T_CH, 1);
    conv3x3_k<<<N_IMG, 256, T_CH * 144 * sizeof(float)>>>(T2, conv3, T1, T_CH, 1);
    conv3x3_k<<<N_IMG, 256, T_CH * 144 * sizeof(float)>>>(T1, conv4, T2, T_CH, 0);

    // Weighted pooling -> output
    rfm_out_k<<<N_IMG, 256>>>(T2, FUSED, (float*)d_out);
}